// round 5
// baseline (speedup 1.0000x reference)
#include <cuda_runtime.h>
#include <cuda_bf16.h>
#include <stdint.h>

#define N_TOK 16384
#define D_DIM 2048
#define H_DIM 1024
#define N_EXP 16

// ------------------------- scratch (device globals; no allocs) -------------
__device__ __nv_bfloat16 g_xh[(size_t)N_TOK * D_DIM];
__device__ __nv_bfloat16 g_xl[(size_t)N_TOK * D_DIM];
__device__ __nv_bfloat16 g_w1h[(size_t)N_EXP * 2 * H_DIM * D_DIM];  // row-interleaved up/gate
__device__ __nv_bfloat16 g_w1l[(size_t)N_EXP * 2 * H_DIM * D_DIM];
__device__ __nv_bfloat16 g_w2th[(size_t)N_EXP * D_DIM * H_DIM];
__device__ __nv_bfloat16 g_w2tl[(size_t)N_EXP * D_DIM * H_DIM];
__device__ __nv_bfloat16 g_hh[(size_t)N_TOK * H_DIM];
__device__ __nv_bfloat16 g_hl[(size_t)N_TOK * H_DIM];

// ------------------------- PTX helpers (compute_103-legal only) ------------
__device__ __forceinline__ uint32_t smem_u32(const void* p) {
    uint32_t a;
    asm("{ .reg .u64 t; cvta.to.shared.u64 t, %1; cvt.u32.u64 %0, t; }"
        : "=r"(a) : "l"(p));
    return a;
}

__device__ __forceinline__ void cp16(uint32_t dst, const void* src) {
    asm volatile("cp.async.cg.shared.global [%0], [%1], 16;\n"
                 :: "r"(dst), "l"(src));
}
__device__ __forceinline__ void cp_commit() {
    asm volatile("cp.async.commit_group;\n" ::: "memory");
}
template <int NN>
__device__ __forceinline__ void cp_wait() {
    asm volatile("cp.async.wait_group %0;\n" :: "n"(NN) : "memory");
}

__device__ __forceinline__ void ldsm4(uint32_t* r, uint32_t addr) {
    asm volatile("ldmatrix.sync.aligned.m8n8.x4.shared.b16 {%0,%1,%2,%3}, [%4];"
                 : "=r"(r[0]), "=r"(r[1]), "=r"(r[2]), "=r"(r[3]) : "r"(addr));
}

__device__ __forceinline__ void mma16816(float* c, const uint32_t* a,
                                         uint32_t b0, uint32_t b1) {
    asm volatile(
        "mma.sync.aligned.m16n8k16.row.col.f32.bf16.bf16.f32 "
        "{%0,%1,%2,%3}, {%4,%5,%6,%7}, {%8,%9}, {%0,%1,%2,%3};"
        : "+f"(c[0]), "+f"(c[1]), "+f"(c[2]), "+f"(c[3])
        : "r"(a[0]), "r"(a[1]), "r"(a[2]), "r"(a[3]), "r"(b0), "r"(b1));
}

// ------------------------- pre-pass kernels --------------------------------
__global__ void __launch_bounds__(256) split_kernel(
    const float* __restrict__ src, __nv_bfloat16* __restrict__ hi,
    __nv_bfloat16* __restrict__ lo) {
    size_t i = (size_t)blockIdx.x * blockDim.x + threadIdx.x;
    float4 v = reinterpret_cast<const float4*>(src)[i];
    __nv_bfloat16 hv[4], lv[4];
    float f[4] = {v.x, v.y, v.z, v.w};
#pragma unroll
    for (int k = 0; k < 4; k++) {
        hv[k] = __float2bfloat16(f[k]);
        lv[k] = __float2bfloat16(f[k] - __bfloat162float(hv[k]));
    }
    reinterpret_cast<uint2*>(hi)[i] = *reinterpret_cast<uint2*>(hv);
    reinterpret_cast<uint2*>(lo)[i] = *reinterpret_cast<uint2*>(lv);
}

// w1 [E,2048,D] (up rows 0-1023, gate 1024-2047) -> row-interleaved, hi/lo
__global__ void __launch_bounds__(256) interleave_split_kernel(
    const float* __restrict__ w, __nv_bfloat16* __restrict__ hi,
    __nv_bfloat16* __restrict__ lo) {
    size_t i = (size_t)blockIdx.x * blockDim.x + threadIdx.x;  // float4 idx
    size_t row = i >> 9;            // D/4 = 512 float4 per row
    size_t c4 = (i & 511) << 2;
    int e = (int)(row >> 11);
    int r = (int)(row & 2047);
    int nr = (r < 1024) ? (2 * r) : (2 * (r - 1024) + 1);
    float4 v = *reinterpret_cast<const float4*>(w + row * D_DIM + c4);
    __nv_bfloat16 hv[4], lv[4];
    float f[4] = {v.x, v.y, v.z, v.w};
#pragma unroll
    for (int k = 0; k < 4; k++) {
        hv[k] = __float2bfloat16(f[k]);
        lv[k] = __float2bfloat16(f[k] - __bfloat162float(hv[k]));
    }
    size_t o4 = (((size_t)e * 2048 + nr) * D_DIM + c4) >> 2;
    reinterpret_cast<uint2*>(hi)[o4] = *reinterpret_cast<uint2*>(hv);
    reinterpret_cast<uint2*>(lo)[o4] = *reinterpret_cast<uint2*>(lv);
}

// w_down [E,H,D] -> w2t [E,D,H], split hi/lo
__global__ void __launch_bounds__(256) transpose_split_kernel(
    const float* __restrict__ w, __nv_bfloat16* __restrict__ th,
    __nv_bfloat16* __restrict__ tl) {
    __shared__ float tile[32][33];
    int e = blockIdx.z, hb = blockIdx.y, db = blockIdx.x;
    int tx = threadIdx.x, ty = threadIdx.y;  // 32 x 8
    const float* src = w + ((size_t)e * H_DIM + hb * 32) * D_DIM + db * 32;
#pragma unroll
    for (int j = 0; j < 32; j += 8)
        tile[ty + j][tx] = src[(size_t)(ty + j) * D_DIM + tx];
    __syncthreads();
    size_t ob = ((size_t)e * D_DIM + db * 32) * H_DIM + hb * 32;
#pragma unroll
    for (int j = 0; j < 32; j += 8) {
        float v = tile[tx][ty + j];
        __nv_bfloat16 hv = __float2bfloat16(v);
        size_t o = ob + (size_t)(ty + j) * H_DIM + tx;
        th[o] = hv;
        tl[o] = __float2bfloat16(v - __bfloat162float(hv));
    }
}

// ------------------------- GEMM (3-term bf16, mma.sync) --------------------
// CTA 128(m) x 128(n), 256 threads (8 warps, 2m x 4n; warp tile 64x32).
// kchunk 32 (64B rows, SW64 swizzle), 3-stage cp.async pipeline, 2 CTAs/SM.
// Terms: Ah*Bh + Al*Bh + Ah*Bl.
#define OFF_AL 8192
#define OFF_BH 16384
#define OFF_BL 24576
#define STAGE_BYTES 32768
#define GEMM_SMEM (3 * STAGE_BYTES)   // 96KB

template <bool FUSE_SILU>
__global__ void __launch_bounds__(256, 2) gemm3_kernel(
    const __nv_bfloat16* __restrict__ Ah, const __nv_bfloat16* __restrict__ Al,
    const __nv_bfloat16* __restrict__ Bh, const __nv_bfloat16* __restrict__ Bl,
    float* __restrict__ C, __nv_bfloat16* __restrict__ Hh,
    __nv_bfloat16* __restrict__ Hl, int K) {
    extern __shared__ char smem[];
    uint32_t sbase = smem_u32(smem);
    int tid = threadIdx.x, wid = tid >> 5, lane = tid & 31;
    int bx = blockIdx.x;
    int e = bx >> 7, rr = bx & 127, mt = rr >> 4, nt = rr & 15;

    const __nv_bfloat16* pAh = Ah + ((size_t)e * 1024 + mt * 128) * (size_t)K;
    const __nv_bfloat16* pAl = Al + ((size_t)e * 1024 + mt * 128) * (size_t)K;
    const __nv_bfloat16* pBh = Bh + ((size_t)e * 2048 + nt * 128) * (size_t)K;
    const __nv_bfloat16* pBl = Bl + ((size_t)e * 2048 + nt * 128) * (size_t)K;

    float acc[4][4][4];
#pragma unroll
    for (int a = 0; a < 4; a++)
#pragma unroll
        for (int b = 0; b < 4; b++)
#pragma unroll
            for (int c = 0; c < 4; c++) acc[a][b][c] = 0.0f;

    // loader mapping: 256 threads; 16B chunk (tid&3), row (tid>>2) in 0..63
    int lrow = tid >> 2, lc16 = tid & 3;
    int wm = wid & 1, wn = wid >> 1;

#define LOAD_STAGE(SB, KC)                                                    \
    do {                                                                      \
        size_t gk = (size_t)(KC)*32 + lc16 * 8;                               \
        _Pragma("unroll") for (int j = 0; j < 2; j++) {                       \
            int r = lrow + 64 * j;                                            \
            uint32_t so = (uint32_t)(r * 64 + lc16 * 16);                     \
            so ^= (so >> 3) & 0x30;                                           \
            cp16((SB) + so, pAh + (size_t)r * K + gk);                        \
            cp16((SB) + OFF_AL + so, pAl + (size_t)r * K + gk);               \
            cp16((SB) + OFF_BH + so, pBh + (size_t)r * K + gk);               \
            cp16((SB) + OFF_BL + so, pBl + (size_t)r * K + gk);               \
        }                                                                     \
    } while (0)

    uint32_t sb[3] = {sbase, sbase + STAGE_BYTES, sbase + 2 * STAGE_BYTES};
    int kiters = K >> 5;
    LOAD_STAGE(sb[0], 0);
    cp_commit();
    LOAD_STAGE(sb[1], 1);
    cp_commit();
    LOAD_STAGE(sb[2], 2);
    cp_commit();

    // ldmatrix lane-address bases (tile-local, pre-swizzle, 64B rows)
    uint32_t aBase =
        (uint32_t)((wm * 64 + (lane & 15)) * 64 + ((lane >> 4) & 1) * 16);
    uint32_t bBase =
        (uint32_t)((wn * 32 + (lane & 7) + ((lane >> 4) & 1) * 8) * 64 +
                   ((lane >> 3) & 1) * 16);

#pragma unroll 1
    for (int kc = 0; kc < kiters; kc++) {
        uint32_t s = sb[kc % 3];
        cp_wait<2>();
        __syncthreads();

#pragma unroll
        for (int k16 = 0; k16 < 2; k16++) {
            uint32_t ah[4][4], al[4][4], bb[2][4];
            uint32_t boff[2];
#pragma unroll
            for (int mf = 0; mf < 4; mf++) {
                uint32_t off = aBase + mf * 1024 + k16 * 32;
                off ^= (off >> 3) & 0x30;
                ldsm4(ah[mf], s + off);
                ldsm4(al[mf], s + OFF_AL + off);
            }
#pragma unroll
            for (int np = 0; np < 2; np++) {
                uint32_t off = bBase + np * 1024 + k16 * 32;
                off ^= (off >> 3) & 0x30;
                boff[np] = off;
                ldsm4(bb[np], s + OFF_BH + off);
            }
            // hh + lh (share Bh fragments)
#pragma unroll
            for (int mf = 0; mf < 4; mf++)
#pragma unroll
                for (int np = 0; np < 2; np++) {
                    mma16816(acc[mf][2 * np], ah[mf], bb[np][0], bb[np][1]);
                    mma16816(acc[mf][2 * np + 1], ah[mf], bb[np][2], bb[np][3]);
                }
#pragma unroll
            for (int mf = 0; mf < 4; mf++)
#pragma unroll
                for (int np = 0; np < 2; np++) {
                    mma16816(acc[mf][2 * np], al[mf], bb[np][0], bb[np][1]);
                    mma16816(acc[mf][2 * np + 1], al[mf], bb[np][2], bb[np][3]);
                }
            // hl (reload B as Bl)
#pragma unroll
            for (int np = 0; np < 2; np++) ldsm4(bb[np], s + OFF_BL + boff[np]);
#pragma unroll
            for (int mf = 0; mf < 4; mf++)
#pragma unroll
                for (int np = 0; np < 2; np++) {
                    mma16816(acc[mf][2 * np], ah[mf], bb[np][0], bb[np][1]);
                    mma16816(acc[mf][2 * np + 1], ah[mf], bb[np][2], bb[np][3]);
                }
        }
        __syncthreads();
        if (kc + 3 < kiters) LOAD_STAGE(sb[kc % 3], kc + 3);
        cp_commit();
    }

    // ---- epilogue ----
    int row0 = wm * 64 + (lane >> 2);
    if (FUSE_SILU) {
        // interleaved cols: even = up, odd = gate. h = up * gate * sigmoid(gate)
        size_t grow0 = (size_t)e * 1024 + mt * 128 + row0;
        int hcol = nt * 64 + wn * 16 + (lane & 3);
#pragma unroll
        for (int mf = 0; mf < 4; mf++)
#pragma unroll
            for (int nf = 0; nf < 4; nf++) {
                size_t r = grow0 + mf * 16;
                int hc = hcol + nf * 4;
                float u0 = acc[mf][nf][0], g0 = acc[mf][nf][1];
                float u1 = acc[mf][nf][2], g1 = acc[mf][nf][3];
                float h0 = u0 * g0 * (1.0f / (1.0f + __expf(-g0)));
                float h1 = u1 * g1 * (1.0f / (1.0f + __expf(-g1)));
                __nv_bfloat16 h0h = __float2bfloat16(h0);
                __nv_bfloat16 h1h = __float2bfloat16(h1);
                Hh[r * H_DIM + hc] = h0h;
                Hl[r * H_DIM + hc] =
                    __float2bfloat16(h0 - __bfloat162float(h0h));
                Hh[(r + 8) * H_DIM + hc] = h1h;
                Hl[(r + 8) * H_DIM + hc] =
                    __float2bfloat16(h1 - __bfloat162float(h1h));
            }
    } else {
        float* pC = C + ((size_t)e * 1024 + mt * 128) * 2048 + nt * 128;
        int col0 = wn * 32 + (lane & 3) * 2;
#pragma unroll
        for (int mf = 0; mf < 4; mf++)
#pragma unroll
            for (int nf = 0; nf < 4; nf++) {
                int r = row0 + mf * 16, c = col0 + nf * 8;
                float2 v0 = {acc[mf][nf][0], acc[mf][nf][1]};
                float2 v1 = {acc[mf][nf][2], acc[mf][nf][3]};
                *reinterpret_cast<float2*>(pC + (size_t)r * 2048 + c) = v0;
                *reinterpret_cast<float2*>(pC + (size_t)(r + 8) * 2048 + c) = v1;
            }
    }
#undef LOAD_STAGE
}

// ------------------------- launch ------------------------------------------
extern "C" void kernel_launch(void* const* d_in, const int* in_sizes, int n_in,
                              void* d_out, int out_size) {
    (void)in_sizes; (void)n_in; (void)out_size;
    const float* x = (const float*)d_in[0];
    const float* w1 = (const float*)d_in[1];
    const float* w2 = (const float*)d_in[2];
    float* out = (float*)d_out;

    cudaFuncSetAttribute(gemm3_kernel<true>,
                         cudaFuncAttributeMaxDynamicSharedMemorySize, GEMM_SMEM);
    cudaFuncSetAttribute(gemm3_kernel<false>,
                         cudaFuncAttributeMaxDynamicSharedMemorySize, GEMM_SMEM);

    __nv_bfloat16 *xh, *xl, *w1h, *w1l, *w2th, *w2tl, *hh, *hl;
    cudaGetSymbolAddress((void**)&xh, g_xh);
    cudaGetSymbolAddress((void**)&xl, g_xl);
    cudaGetSymbolAddress((void**)&w1h, g_w1h);
    cudaGetSymbolAddress((void**)&w1l, g_w1l);
    cudaGetSymbolAddress((void**)&w2th, g_w2th);
    cudaGetSymbolAddress((void**)&w2tl, g_w2tl);
    cudaGetSymbolAddress((void**)&hh, g_hh);
    cudaGetSymbolAddress((void**)&hl, g_hl);

    // pre-pass: bf16 hi/lo splits (w1 row-interleaved; w2 transposed)
    split_kernel<<<32768, 256>>>(x, xh, xl);
    interleave_split_kernel<<<65536, 256>>>(w1, w1h, w1l);
    transpose_split_kernel<<<dim3(64, 32, 16), dim3(32, 8)>>>(w2, w2th, w2tl);

    // GEMM1: up/gate + fused silu -> h (bf16 hi/lo). grid: E * 8mt * 16nt
    gemm3_kernel<true><<<N_EXP * 128, 256, GEMM_SMEM>>>(
        xh, xl, w1h, w1l, nullptr, hh, hl, D_DIM);
    // GEMM2: out = h @ w2t^T. grid: E * 8mt * 16nt
    gemm3_kernel<false><<<N_EXP * 128, 256, GEMM_SMEM>>>(
        hh, hl, w2th, w2tl, out, nullptr, nullptr, H_DIM);
}

// round 6
// speedup vs baseline: 1.4610x; 1.4610x over previous
#include <cuda_runtime.h>
#include <cuda_fp16.h>
#include <stdint.h>

#define N_TOK 16384
#define D_DIM 2048
#define H_DIM 1024
#define N_EXP 16

// ------------------------- scratch (device globals; no allocs) -------------
__device__ __half g_xh[(size_t)N_TOK * D_DIM];
__device__ __half g_xl[(size_t)N_TOK * D_DIM];
__device__ __half g_w1h[(size_t)N_EXP * 2 * H_DIM * D_DIM];  // row-interleaved up/gate
__device__ __half g_w2th[(size_t)N_EXP * D_DIM * H_DIM];     // transposed w_down
__device__ __half g_hh[(size_t)N_TOK * H_DIM];
__device__ __half g_hl[(size_t)N_TOK * H_DIM];

// ------------------------- PTX helpers (compute_103-legal only) ------------
__device__ __forceinline__ uint32_t smem_u32(const void* p) {
    uint32_t a;
    asm("{ .reg .u64 t; cvta.to.shared.u64 t, %1; cvt.u32.u64 %0, t; }"
        : "=r"(a) : "l"(p));
    return a;
}

__device__ __forceinline__ void cp16(uint32_t dst, const void* src) {
    asm volatile("cp.async.cg.shared.global [%0], [%1], 16;\n"
                 :: "r"(dst), "l"(src));
}
__device__ __forceinline__ void cp_commit() {
    asm volatile("cp.async.commit_group;\n" ::: "memory");
}
template <int NN>
__device__ __forceinline__ void cp_wait() {
    asm volatile("cp.async.wait_group %0;\n" :: "n"(NN) : "memory");
}

__device__ __forceinline__ void ldsm4(uint32_t* r, uint32_t addr) {
    asm volatile("ldmatrix.sync.aligned.m8n8.x4.shared.b16 {%0,%1,%2,%3}, [%4];"
                 : "=r"(r[0]), "=r"(r[1]), "=r"(r[2]), "=r"(r[3]) : "r"(addr));
}

__device__ __forceinline__ void mma16816(float* c, const uint32_t* a,
                                         uint32_t b0, uint32_t b1) {
    asm volatile(
        "mma.sync.aligned.m16n8k16.row.col.f32.f16.f16.f32 "
        "{%0,%1,%2,%3}, {%4,%5,%6,%7}, {%8,%9}, {%0,%1,%2,%3};"
        : "+f"(c[0]), "+f"(c[1]), "+f"(c[2]), "+f"(c[3])
        : "r"(a[0]), "r"(a[1]), "r"(a[2]), "r"(a[3]), "r"(b0), "r"(b1));
}

// ------------------------- pre-pass kernels --------------------------------
// fp32 -> fp16 hi/lo exact split
__global__ void __launch_bounds__(256) split_kernel(
    const float* __restrict__ src, __half* __restrict__ hi,
    __half* __restrict__ lo) {
    size_t i = (size_t)blockIdx.x * blockDim.x + threadIdx.x;
    float4 v = reinterpret_cast<const float4*>(src)[i];
    __half hv[4], lv[4];
    float f[4] = {v.x, v.y, v.z, v.w};
#pragma unroll
    for (int k = 0; k < 4; k++) {
        hv[k] = __float2half(f[k]);
        lv[k] = __float2half(f[k] - __half2float(hv[k]));
    }
    reinterpret_cast<uint2*>(hi)[i] = *reinterpret_cast<uint2*>(hv);
    reinterpret_cast<uint2*>(lo)[i] = *reinterpret_cast<uint2*>(lv);
}

// w1 [E,2048,D] (up rows 0-1023, gate 1024-2047) -> row-interleaved fp16
__global__ void __launch_bounds__(256) interleave_cvt_kernel(
    const float* __restrict__ w, __half* __restrict__ dst) {
    size_t i = (size_t)blockIdx.x * blockDim.x + threadIdx.x;  // float4 idx
    size_t row = i >> 9;            // D/4 = 512 float4 per row
    size_t c4 = (i & 511) << 2;
    int e = (int)(row >> 11);
    int r = (int)(row & 2047);
    int nr = (r < 1024) ? (2 * r) : (2 * (r - 1024) + 1);
    float4 v = *reinterpret_cast<const float4*>(w + row * D_DIM + c4);
    __half hv[4];
    float f[4] = {v.x, v.y, v.z, v.w};
#pragma unroll
    for (int k = 0; k < 4; k++) hv[k] = __float2half(f[k]);
    size_t o4 = (((size_t)e * 2048 + nr) * D_DIM + c4) >> 2;
    reinterpret_cast<uint2*>(dst)[o4] = *reinterpret_cast<uint2*>(hv);
}

// w_down [E,H,D] -> w2t [E,D,H] fp16
__global__ void __launch_bounds__(256) transpose_cvt_kernel(
    const float* __restrict__ w, __half* __restrict__ th) {
    __shared__ float tile[32][33];
    int e = blockIdx.z, hb = blockIdx.y, db = blockIdx.x;
    int tx = threadIdx.x, ty = threadIdx.y;  // 32 x 8
    const float* src = w + ((size_t)e * H_DIM + hb * 32) * D_DIM + db * 32;
#pragma unroll
    for (int j = 0; j < 32; j += 8)
        tile[ty + j][tx] = src[(size_t)(ty + j) * D_DIM + tx];
    __syncthreads();
    size_t ob = ((size_t)e * D_DIM + db * 32) * H_DIM + hb * 32;
#pragma unroll
    for (int j = 0; j < 32; j += 8)
        th[ob + (size_t)(ty + j) * H_DIM + tx] = __float2half(tile[tx][ty + j]);
}

// ------------------------- GEMM (2-term fp16, mma.sync) --------------------
// C = (Ah+Al) x Bh^T.  CTA 128(m) x 256(n), 512 threads (16 warps, 4m x 4n,
// warp tile 32x64). kchunk 64 (128B rows, SW128). 3-stage ring, 1 barrier/chunk.
#define OFF_AL 16384
#define OFF_B  32768
#define STAGE_BYTES 65536        // Ah(16K) + Al(16K) + B(32K)
#define GEMM_SMEM (3 * STAGE_BYTES)  // 192KB

template <bool FUSE_SILU>
__global__ void __launch_bounds__(512, 1) gemm2t_kernel(
    const __half* __restrict__ Ah, const __half* __restrict__ Al,
    const __half* __restrict__ B, float* __restrict__ C,
    __half* __restrict__ Hh, __half* __restrict__ Hl, int K) {
    extern __shared__ char smem[];
    uint32_t sbase = smem_u32(smem);
    int tid = threadIdx.x, wid = tid >> 5, lane = tid & 31;
    int bx = blockIdx.x;
    int e = bx >> 6, rr = bx & 63, mt = rr >> 3, nt = rr & 7;

    const __half* pAh = Ah + ((size_t)e * 1024 + mt * 128) * (size_t)K;
    const __half* pAl = Al + ((size_t)e * 1024 + mt * 128) * (size_t)K;
    const __half* pB = B + ((size_t)e * 2048 + nt * 256) * (size_t)K;

    float acc[2][8][4];
#pragma unroll
    for (int a = 0; a < 2; a++)
#pragma unroll
        for (int b = 0; b < 8; b++)
#pragma unroll
            for (int c = 0; c < 4; c++) acc[a][b][c] = 0.0f;

    // loader mapping: 512 threads; 16B chunk (tid&7), row (tid>>3) in 0..63
    int lrow = tid >> 3, lc16 = tid & 7;
    int wm = wid & 3, wn = wid >> 2;

#define LOAD_STAGE(SB, KC)                                                    \
    do {                                                                      \
        size_t gk = (size_t)(KC)*64 + lc16 * 8;                               \
        _Pragma("unroll") for (int j = 0; j < 2; j++) {                       \
            int r = lrow + 64 * j;                                            \
            uint32_t so = (uint32_t)(r * 128 + lc16 * 16);                    \
            so ^= (so >> 3) & 0x70;                                           \
            cp16((SB) + so, pAh + (size_t)r * K + gk);                        \
            cp16((SB) + OFF_AL + so, pAl + (size_t)r * K + gk);               \
        }                                                                     \
        _Pragma("unroll") for (int j = 0; j < 4; j++) {                       \
            int r = lrow + 64 * j;                                            \
            uint32_t so = (uint32_t)(r * 128 + lc16 * 16);                    \
            so ^= (so >> 3) & 0x70;                                           \
            cp16((SB) + OFF_B + so, pB + (size_t)r * K + gk);                 \
        }                                                                     \
    } while (0)

    uint32_t sb[3] = {sbase, sbase + STAGE_BYTES, sbase + 2 * STAGE_BYTES};
    int kiters = K >> 6;
    LOAD_STAGE(sb[0], 0);
    cp_commit();
    LOAD_STAGE(sb[1], 1);
    cp_commit();

    // ldmatrix lane-address bases (tile-local, pre-swizzle)
    uint32_t aBase =
        (uint32_t)((wm * 32 + (lane & 15)) * 128 + ((lane >> 4) & 1) * 16);
    uint32_t bBase =
        (uint32_t)((wn * 64 + (lane & 7) + ((lane >> 4) & 1) * 8) * 128 +
                   ((lane >> 3) & 1) * 16);

#pragma unroll 1
    for (int kc = 0; kc < kiters; kc++) {
        uint32_t s = sb[kc % 3];
        cp_wait<1>();
        __syncthreads();  // single barrier per chunk: ring stage being loaded
                          // next was consumed in the PREVIOUS iteration.

#pragma unroll
        for (int k16 = 0; k16 < 4; k16++) {
            uint32_t ah[2][4], al[2][4], bb[4][4];
#pragma unroll
            for (int mf = 0; mf < 2; mf++) {
                uint32_t off = aBase + mf * 2048 + k16 * 32;
                off ^= (off >> 3) & 0x70;
                ldsm4(ah[mf], s + off);
                ldsm4(al[mf], s + OFF_AL + off);
            }
#pragma unroll
            for (int np = 0; np < 4; np++) {
                uint32_t off = bBase + np * 2048 + k16 * 32;
                off ^= (off >> 3) & 0x70;
                ldsm4(bb[np], s + OFF_B + off);
            }
#pragma unroll
            for (int mf = 0; mf < 2; mf++)
#pragma unroll
                for (int np = 0; np < 4; np++) {
                    mma16816(acc[mf][2 * np], ah[mf], bb[np][0], bb[np][1]);
                    mma16816(acc[mf][2 * np + 1], ah[mf], bb[np][2], bb[np][3]);
                }
#pragma unroll
            for (int mf = 0; mf < 2; mf++)
#pragma unroll
                for (int np = 0; np < 4; np++) {
                    mma16816(acc[mf][2 * np], al[mf], bb[np][0], bb[np][1]);
                    mma16816(acc[mf][2 * np + 1], al[mf], bb[np][2], bb[np][3]);
                }
        }
        if (kc + 2 < kiters) LOAD_STAGE(sb[(kc + 2) % 3], kc + 2);
        cp_commit();
    }

    // ---- epilogue ----
    int row0 = wm * 32 + (lane >> 2);
    if (FUSE_SILU) {
        // interleaved cols: even = up, odd = gate. h = up * gate * sigmoid(gate)
        size_t grow0 = (size_t)e * 1024 + mt * 128 + row0;
        int hcol = nt * 128 + wn * 32 + (lane & 3);
#pragma unroll
        for (int mf = 0; mf < 2; mf++)
#pragma unroll
            for (int nf = 0; nf < 8; nf++) {
                size_t r = grow0 + mf * 16;
                int hc = hcol + nf * 4;
                float u0 = acc[mf][nf][0], g0 = acc[mf][nf][1];
                float u1 = acc[mf][nf][2], g1 = acc[mf][nf][3];
                float h0 = u0 * g0 * (1.0f / (1.0f + __expf(-g0)));
                float h1 = u1 * g1 * (1.0f / (1.0f + __expf(-g1)));
                __half h0h = __float2half(h0);
                __half h1h = __float2half(h1);
                Hh[r * H_DIM + hc] = h0h;
                Hl[r * H_DIM + hc] = __float2half(h0 - __half2float(h0h));
                Hh[(r + 8) * H_DIM + hc] = h1h;
                Hl[(r + 8) * H_DIM + hc] = __float2half(h1 - __half2float(h1h));
            }
    } else {
        float* pC = C + ((size_t)e * 1024 + mt * 128) * 2048 + nt * 256;
        int col0 = wn * 64 + (lane & 3) * 2;
#pragma unroll
        for (int mf = 0; mf < 2; mf++)
#pragma unroll
            for (int nf = 0; nf < 8; nf++) {
                int r = row0 + mf * 16, c = col0 + nf * 8;
                float2 v0 = {acc[mf][nf][0], acc[mf][nf][1]};
                float2 v1 = {acc[mf][nf][2], acc[mf][nf][3]};
                *reinterpret_cast<float2*>(pC + (size_t)r * 2048 + c) = v0;
                *reinterpret_cast<float2*>(pC + (size_t)(r + 8) * 2048 + c) = v1;
            }
    }
#undef LOAD_STAGE
}

// ------------------------- launch ------------------------------------------
extern "C" void kernel_launch(void* const* d_in, const int* in_sizes, int n_in,
                              void* d_out, int out_size) {
    (void)in_sizes; (void)n_in; (void)out_size;
    const float* x = (const float*)d_in[0];
    const float* w1 = (const float*)d_in[1];
    const float* w2 = (const float*)d_in[2];
    float* out = (float*)d_out;

    cudaFuncSetAttribute(gemm2t_kernel<true>,
                         cudaFuncAttributeMaxDynamicSharedMemorySize, GEMM_SMEM);
    cudaFuncSetAttribute(gemm2t_kernel<false>,
                         cudaFuncAttributeMaxDynamicSharedMemorySize, GEMM_SMEM);

    __half *xh, *xl, *w1h, *w2th, *hh, *hl;
    cudaGetSymbolAddress((void**)&xh, g_xh);
    cudaGetSymbolAddress((void**)&xl, g_xl);
    cudaGetSymbolAddress((void**)&w1h, g_w1h);
    cudaGetSymbolAddress((void**)&w2th, g_w2th);
    cudaGetSymbolAddress((void**)&hh, g_hh);
    cudaGetSymbolAddress((void**)&hl, g_hl);

    // pre-pass: x -> fp16 hi/lo; w1 -> interleaved fp16; w2 -> transposed fp16
    split_kernel<<<32768, 256>>>(x, xh, xl);
    interleave_cvt_kernel<<<65536, 256>>>(w1, w1h);
    transpose_cvt_kernel<<<dim3(64, 32, 16), dim3(32, 8)>>>(w2, w2th);

    // GEMM1: up/gate + fused silu -> h (fp16 hi/lo). grid: E * 8mt * 8nt
    gemm2t_kernel<true><<<N_EXP * 64, 512, GEMM_SMEM>>>(
        xh, xl, w1h, nullptr, hh, hl, D_DIM);
    // GEMM2: out = h @ w2t^T. grid: E * 8mt * 8nt
    gemm2t_kernel<false><<<N_EXP * 64, 512, GEMM_SMEM>>>(
        hh, hl, w2th, out, nullptr, nullptr, H_DIM);
}

// round 7
// speedup vs baseline: 2.3220x; 1.5893x over previous
#include <cuda_runtime.h>
#include <cuda_fp16.h>
#include <stdint.h>

#define N_TOK 16384
#define D_DIM 2048
#define H_DIM 1024
#define N_EXP 16

// ------------------------- scratch (device globals; no allocs) -------------
__device__ __half g_xh[(size_t)N_TOK * D_DIM];
__device__ __half g_w1h[(size_t)N_EXP * 2 * H_DIM * D_DIM];  // row-interleaved up/gate
__device__ __half g_w2th[(size_t)N_EXP * D_DIM * H_DIM];     // transposed w_down
__device__ __half g_hh[(size_t)N_TOK * H_DIM];

// ------------------------- PTX helpers (compute_103-legal only) ------------
__device__ __forceinline__ uint32_t smem_u32(const void* p) {
    uint32_t a;
    asm("{ .reg .u64 t; cvta.to.shared.u64 t, %1; cvt.u32.u64 %0, t; }"
        : "=r"(a) : "l"(p));
    return a;
}

__device__ __forceinline__ void cp16(uint32_t dst, const void* src) {
    asm volatile("cp.async.cg.shared.global [%0], [%1], 16;\n"
                 :: "r"(dst), "l"(src));
}
__device__ __forceinline__ void cp_commit() {
    asm volatile("cp.async.commit_group;\n" ::: "memory");
}
template <int NN>
__device__ __forceinline__ void cp_wait() {
    asm volatile("cp.async.wait_group %0;\n" :: "n"(NN) : "memory");
}

__device__ __forceinline__ void ldsm4(uint32_t* r, uint32_t addr) {
    asm volatile("ldmatrix.sync.aligned.m8n8.x4.shared.b16 {%0,%1,%2,%3}, [%4];"
                 : "=r"(r[0]), "=r"(r[1]), "=r"(r[2]), "=r"(r[3]) : "r"(addr));
}

__device__ __forceinline__ void mma16816(float* c, const uint32_t* a,
                                         uint32_t b0, uint32_t b1) {
    asm volatile(
        "mma.sync.aligned.m16n8k16.row.col.f32.f16.f16.f32 "
        "{%0,%1,%2,%3}, {%4,%5,%6,%7}, {%8,%9}, {%0,%1,%2,%3};"
        : "+f"(c[0]), "+f"(c[1]), "+f"(c[2]), "+f"(c[3])
        : "r"(a[0]), "r"(a[1]), "r"(a[2]), "r"(a[3]), "r"(b0), "r"(b1));
}

// ------------------------- pre-pass kernels --------------------------------
// fp32 -> fp16
__global__ void __launch_bounds__(256) cvt_kernel(
    const float* __restrict__ src, __half* __restrict__ dst) {
    size_t i = (size_t)blockIdx.x * blockDim.x + threadIdx.x;
    float4 v = reinterpret_cast<const float4*>(src)[i];
    __half hv[4];
    float f[4] = {v.x, v.y, v.z, v.w};
#pragma unroll
    for (int k = 0; k < 4; k++) hv[k] = __float2half(f[k]);
    reinterpret_cast<uint2*>(dst)[i] = *reinterpret_cast<uint2*>(hv);
}

// w1 [E,2048,D] (up rows 0-1023, gate 1024-2047) -> row-interleaved fp16
__global__ void __launch_bounds__(256) interleave_cvt_kernel(
    const float* __restrict__ w, __half* __restrict__ dst) {
    size_t i = (size_t)blockIdx.x * blockDim.x + threadIdx.x;  // float4 idx
    size_t row = i >> 9;            // D/4 = 512 float4 per row
    size_t c4 = (i & 511) << 2;
    int e = (int)(row >> 11);
    int r = (int)(row & 2047);
    int nr = (r < 1024) ? (2 * r) : (2 * (r - 1024) + 1);
    float4 v = *reinterpret_cast<const float4*>(w + row * D_DIM + c4);
    __half hv[4];
    float f[4] = {v.x, v.y, v.z, v.w};
#pragma unroll
    for (int k = 0; k < 4; k++) hv[k] = __float2half(f[k]);
    size_t o4 = (((size_t)e * 2048 + nr) * D_DIM + c4) >> 2;
    reinterpret_cast<uint2*>(dst)[o4] = *reinterpret_cast<uint2*>(hv);
}

// w_down [E,H,D] -> w2t [E,D,H] fp16
__global__ void __launch_bounds__(256) transpose_cvt_kernel(
    const float* __restrict__ w, __half* __restrict__ th) {
    __shared__ float tile[32][33];
    int e = blockIdx.z, hb = blockIdx.y, db = blockIdx.x;
    int tx = threadIdx.x, ty = threadIdx.y;  // 32 x 8
    const float* src = w + ((size_t)e * H_DIM + hb * 32) * D_DIM + db * 32;
#pragma unroll
    for (int j = 0; j < 32; j += 8)
        tile[ty + j][tx] = src[(size_t)(ty + j) * D_DIM + tx];
    __syncthreads();
    size_t ob = ((size_t)e * D_DIM + db * 32) * H_DIM + hb * 32;
#pragma unroll
    for (int j = 0; j < 32; j += 8)
        th[ob + (size_t)(ty + j) * H_DIM + tx] = __float2half(tile[tx][ty + j]);
}

// ------------------------- GEMM (fp16, mma.sync) ---------------------------
// C = A x B^T.  CTA 128(m) x 256(n), 512 threads (16 warps, 4m x 4n,
// warp tile 32x64). kchunk 64 (128B rows, SW128). 4-stage ring, 1 barrier/chunk.
#define OFF_B  16384
#define STAGE_BYTES 49152            // A(16K) + B(32K)
#define GEMM_SMEM (4 * STAGE_BYTES)  // 192KB

template <bool FUSE_SILU>
__global__ void __launch_bounds__(512, 1) gemmf_kernel(
    const __half* __restrict__ A, const __half* __restrict__ B,
    float* __restrict__ C, __half* __restrict__ H, int K) {
    extern __shared__ char smem[];
    uint32_t sbase = smem_u32(smem);
    int tid = threadIdx.x, wid = tid >> 5, lane = tid & 31;
    int bx = blockIdx.x;
    int e = bx >> 6, rr = bx & 63, mt = rr >> 3, nt = rr & 7;

    const __half* pA = A + ((size_t)e * 1024 + mt * 128) * (size_t)K;
    const __half* pB = B + ((size_t)e * 2048 + nt * 256) * (size_t)K;

    float acc[2][8][4];
#pragma unroll
    for (int a = 0; a < 2; a++)
#pragma unroll
        for (int b = 0; b < 8; b++)
#pragma unroll
            for (int c = 0; c < 4; c++) acc[a][b][c] = 0.0f;

    // loader mapping: 512 threads; 16B chunk (tid&7), row (tid>>3) in 0..63
    int lrow = tid >> 3, lc16 = tid & 7;
    int wm = wid & 3, wn = wid >> 2;

#define LOAD_STAGE(SB, KC)                                                    \
    do {                                                                      \
        size_t gk = (size_t)(KC)*64 + lc16 * 8;                               \
        _Pragma("unroll") for (int j = 0; j < 2; j++) {                       \
            int r = lrow + 64 * j;                                            \
            uint32_t so = (uint32_t)(r * 128 + lc16 * 16);                    \
            so ^= (so >> 3) & 0x70;                                           \
            cp16((SB) + so, pA + (size_t)r * K + gk);                         \
        }                                                                     \
        _Pragma("unroll") for (int j = 0; j < 4; j++) {                       \
            int r = lrow + 64 * j;                                            \
            uint32_t so = (uint32_t)(r * 128 + lc16 * 16);                    \
            so ^= (so >> 3) & 0x70;                                           \
            cp16((SB) + OFF_B + so, pB + (size_t)r * K + gk);                 \
        }                                                                     \
    } while (0)

    uint32_t sb[4] = {sbase, sbase + STAGE_BYTES, sbase + 2 * STAGE_BYTES,
                      sbase + 3 * STAGE_BYTES};
    int kiters = K >> 6;
    LOAD_STAGE(sb[0], 0);
    cp_commit();
    LOAD_STAGE(sb[1], 1);
    cp_commit();
    LOAD_STAGE(sb[2], 2);
    cp_commit();

    // ldmatrix lane-address bases (tile-local, pre-swizzle)
    uint32_t aBase =
        (uint32_t)((wm * 32 + (lane & 15)) * 128 + ((lane >> 4) & 1) * 16);
    uint32_t bBase =
        (uint32_t)((wn * 64 + (lane & 7) + ((lane >> 4) & 1) * 8) * 128 +
                   ((lane >> 3) & 1) * 16);

#pragma unroll 1
    for (int kc = 0; kc < kiters; kc++) {
        uint32_t s = sb[kc & 3];
        cp_wait<2>();
        __syncthreads();  // ring: stage loaded next was consumed 3 iters ago

#pragma unroll
        for (int k16 = 0; k16 < 4; k16++) {
            uint32_t ah[2][4], bb[4][4];
#pragma unroll
            for (int mf = 0; mf < 2; mf++) {
                uint32_t off = aBase + mf * 2048 + k16 * 32;
                off ^= (off >> 3) & 0x70;
                ldsm4(ah[mf], s + off);
            }
#pragma unroll
            for (int np = 0; np < 4; np++) {
                uint32_t off = bBase + np * 2048 + k16 * 32;
                off ^= (off >> 3) & 0x70;
                ldsm4(bb[np], s + OFF_B + off);
            }
#pragma unroll
            for (int mf = 0; mf < 2; mf++)
#pragma unroll
                for (int np = 0; np < 4; np++) {
                    mma16816(acc[mf][2 * np], ah[mf], bb[np][0], bb[np][1]);
                    mma16816(acc[mf][2 * np + 1], ah[mf], bb[np][2], bb[np][3]);
                }
        }
        if (kc + 3 < kiters) LOAD_STAGE(sb[(kc + 3) & 3], kc + 3);
        cp_commit();
    }

    // ---- epilogue ----
    int row0 = wm * 32 + (lane >> 2);
    if (FUSE_SILU) {
        // interleaved cols: even = up, odd = gate. h = up * gate * sigmoid(gate)
        size_t grow0 = (size_t)e * 1024 + mt * 128 + row0;
        int hcol = nt * 128 + wn * 32 + (lane & 3);
#pragma unroll
        for (int mf = 0; mf < 2; mf++)
#pragma unroll
            for (int nf = 0; nf < 8; nf++) {
                size_t r = grow0 + mf * 16;
                int hc = hcol + nf * 4;
                float u0 = acc[mf][nf][0], g0 = acc[mf][nf][1];
                float u1 = acc[mf][nf][2], g1 = acc[mf][nf][3];
                float h0 = u0 * g0 * (1.0f / (1.0f + __expf(-g0)));
                float h1 = u1 * g1 * (1.0f / (1.0f + __expf(-g1)));
                H[r * H_DIM + hc] = __float2half(h0);
                H[(r + 8) * H_DIM + hc] = __float2half(h1);
            }
    } else {
        float* pC = C + ((size_t)e * 1024 + mt * 128) * 2048 + nt * 256;
        int col0 = wn * 64 + (lane & 3) * 2;
#pragma unroll
        for (int mf = 0; mf < 2; mf++)
#pragma unroll
            for (int nf = 0; nf < 8; nf++) {
                int r = row0 + mf * 16, c = col0 + nf * 8;
                float2 v0 = {acc[mf][nf][0], acc[mf][nf][1]};
                float2 v1 = {acc[mf][nf][2], acc[mf][nf][3]};
                *reinterpret_cast<float2*>(pC + (size_t)r * 2048 + c) = v0;
                *reinterpret_cast<float2*>(pC + (size_t)(r + 8) * 2048 + c) = v1;
            }
    }
#undef LOAD_STAGE
}

// ------------------------- launch ------------------------------------------
extern "C" void kernel_launch(void* const* d_in, const int* in_sizes, int n_in,
                              void* d_out, int out_size) {
    (void)in_sizes; (void)n_in; (void)out_size;
    const float* x = (const float*)d_in[0];
    const float* w1 = (const float*)d_in[1];
    const float* w2 = (const float*)d_in[2];
    float* out = (float*)d_out;

    cudaFuncSetAttribute(gemmf_kernel<true>,
                         cudaFuncAttributeMaxDynamicSharedMemorySize, GEMM_SMEM);
    cudaFuncSetAttribute(gemmf_kernel<false>,
                         cudaFuncAttributeMaxDynamicSharedMemorySize, GEMM_SMEM);

    __half *xh, *w1h, *w2th, *hh;
    cudaGetSymbolAddress((void**)&xh, g_xh);
    cudaGetSymbolAddress((void**)&w1h, g_w1h);
    cudaGetSymbolAddress((void**)&w2th, g_w2th);
    cudaGetSymbolAddress((void**)&hh, g_hh);

    // pre-pass: x -> fp16; w1 -> interleaved fp16; w2 -> transposed fp16
    cvt_kernel<<<32768, 256>>>(x, xh);
    interleave_cvt_kernel<<<65536, 256>>>(w1, w1h);
    transpose_cvt_kernel<<<dim3(64, 32, 16), dim3(32, 8)>>>(w2, w2th);

    // GEMM1: up/gate + fused silu -> h (fp16). grid: E * 8mt * 8nt
    gemmf_kernel<true><<<N_EXP * 64, 512, GEMM_SMEM>>>(
        xh, w1h, nullptr, hh, D_DIM);
    // GEMM2: out = h @ w2t^T. grid: E * 8mt * 8nt
    gemmf_kernel<false><<<N_EXP * 64, 512, GEMM_SMEM>>>(
        hh, w2th, out, nullptr, H_DIM);
}

// round 9
// speedup vs baseline: 2.3465x; 1.0105x over previous
#include <cuda_runtime.h>
#include <cuda_fp16.h>
#include <stdint.h>

#define N_TOK 16384
#define D_DIM 2048
#define H_DIM 1024
#define N_EXP 16

// ------------------------- scratch (device globals; no allocs) -------------
__device__ __half g_xh[(size_t)N_TOK * D_DIM];
__device__ __half g_w1h[(size_t)N_EXP * 2 * H_DIM * D_DIM];  // row-interleaved up/gate
__device__ __half g_w2th[(size_t)N_EXP * D_DIM * H_DIM];     // transposed w_down
__device__ __half g_hh[(size_t)N_TOK * H_DIM];

// ------------------------- PTX helpers (compute_103-legal only) ------------
__device__ __forceinline__ uint32_t smem_u32(const void* p) {
    uint32_t a;
    asm("{ .reg .u64 t; cvta.to.shared.u64 t, %1; cvt.u32.u64 %0, t; }"
        : "=r"(a) : "l"(p));
    return a;
}

__device__ __forceinline__ void cp16(uint32_t dst, const void* src) {
    asm volatile("cp.async.cg.shared.global [%0], [%1], 16;\n"
                 :: "r"(dst), "l"(src));
}
__device__ __forceinline__ void cp_commit() {
    asm volatile("cp.async.commit_group;\n" ::: "memory");
}
template <int NN>
__device__ __forceinline__ void cp_wait() {
    asm volatile("cp.async.wait_group %0;\n" :: "n"(NN) : "memory");
}

__device__ __forceinline__ void ldsm4(uint32_t* r, uint32_t addr) {
    asm volatile("ldmatrix.sync.aligned.m8n8.x4.shared.b16 {%0,%1,%2,%3}, [%4];"
                 : "=r"(r[0]), "=r"(r[1]), "=r"(r[2]), "=r"(r[3]) : "r"(addr));
}

__device__ __forceinline__ void mma16816(float* c, const uint32_t* a,
                                         uint32_t b0, uint32_t b1) {
    asm volatile(
        "mma.sync.aligned.m16n8k16.row.col.f32.f16.f16.f32 "
        "{%0,%1,%2,%3}, {%4,%5,%6,%7}, {%8,%9}, {%0,%1,%2,%3};"
        : "+f"(c[0]), "+f"(c[1]), "+f"(c[2]), "+f"(c[3])
        : "r"(a[0]), "r"(a[1]), "r"(a[2]), "r"(a[3]), "r"(b0), "r"(b1));
}

// ------------------------- pre-pass kernels --------------------------------
__global__ void __launch_bounds__(256) cvt_kernel(
    const float* __restrict__ src, __half* __restrict__ dst) {
    size_t i = (size_t)blockIdx.x * blockDim.x + threadIdx.x;
    float4 v = reinterpret_cast<const float4*>(src)[i];
    __half hv[4];
    float f[4] = {v.x, v.y, v.z, v.w};
#pragma unroll
    for (int k = 0; k < 4; k++) hv[k] = __float2half(f[k]);
    reinterpret_cast<uint2*>(dst)[i] = *reinterpret_cast<uint2*>(hv);
}

// w1 [E,2048,D] (up rows 0-1023, gate 1024-2047) -> row-interleaved fp16
__global__ void __launch_bounds__(256) interleave_cvt_kernel(
    const float* __restrict__ w, __half* __restrict__ dst) {
    size_t i = (size_t)blockIdx.x * blockDim.x + threadIdx.x;  // float4 idx
    size_t row = i >> 9;
    size_t c4 = (i & 511) << 2;
    int e = (int)(row >> 11);
    int r = (int)(row & 2047);
    int nr = (r < 1024) ? (2 * r) : (2 * (r - 1024) + 1);
    float4 v = *reinterpret_cast<const float4*>(w + row * D_DIM + c4);
    __half hv[4];
    float f[4] = {v.x, v.y, v.z, v.w};
#pragma unroll
    for (int k = 0; k < 4; k++) hv[k] = __float2half(f[k]);
    size_t o4 = (((size_t)e * 2048 + nr) * D_DIM + c4) >> 2;
    reinterpret_cast<uint2*>(dst)[o4] = *reinterpret_cast<uint2*>(hv);
}

// w_down [E,H,D] -> w2t [E,D,H] fp16
__global__ void __launch_bounds__(256) transpose_cvt_kernel(
    const float* __restrict__ w, __half* __restrict__ th) {
    __shared__ float tile[32][33];
    int e = blockIdx.z, hb = blockIdx.y, db = blockIdx.x;
    int tx = threadIdx.x, ty = threadIdx.y;  // 32 x 8
    const float* src = w + ((size_t)e * H_DIM + hb * 32) * D_DIM + db * 32;
#pragma unroll
    for (int j = 0; j < 32; j += 8)
        tile[ty + j][tx] = src[(size_t)(ty + j) * D_DIM + tx];
    __syncthreads();
    size_t ob = ((size_t)e * D_DIM + db * 32) * H_DIM + hb * 32;
#pragma unroll
    for (int j = 0; j < 32; j += 8)
        th[ob + (size_t)(ty + j) * H_DIM + tx] = __float2half(tile[tx][ty + j]);
}

// ------------------------- GEMM (fp16, mma.sync) ---------------------------
// C = A x B^T.  CTA 128(m) x 256(n), 512 threads (16 warps, 4m x 4n,
// warp tile 32x64). kchunk 64 (128B rows, SW128). 4-stage ring, 1 barrier/chunk.
// K templated: loader strides constant-folded. Fragment double-buffering.
#define OFF_B  16384
#define STAGE_BYTES 49152            // A(16K) + B(32K)
#define GEMM_SMEM (4 * STAGE_BYTES)  // 192KB

template <int K, bool FUSE_SILU>
__global__ void __launch_bounds__(512, 1) gemmf_kernel(
    const __half* __restrict__ A, const __half* __restrict__ B,
    float* __restrict__ C, __half* __restrict__ H) {
    extern __shared__ char smem[];
    uint32_t sbase = smem_u32(smem);
    int tid = threadIdx.x, wid = tid >> 5, lane = tid & 31;
    int bx = blockIdx.x;
    int e = bx >> 6, rr = bx & 63, mt = rr >> 3, nt = rr & 7;

    // per-thread loader global pointers (bytes); constant strides thereafter
    int lrow = tid >> 3, lc16 = tid & 7;
    const char* gA = (const char*)(A + ((size_t)e * 1024 + mt * 128 + lrow) * K +
                                   lc16 * 8);
    const char* gB = (const char*)(B + ((size_t)e * 2048 + nt * 256 + lrow) * K +
                                   lc16 * 8);
    // per-thread loader smem offset (swizzled once; +j*8192 carry-free since
    // soL < 8192)
    uint32_t soL = (uint32_t)(lrow * 128 + lc16 * 16);
    soL ^= (soL >> 3) & 0x70;

    float acc[2][8][4];
#pragma unroll
    for (int a = 0; a < 2; a++)
#pragma unroll
        for (int b = 0; b < 8; b++)
#pragma unroll
            for (int c = 0; c < 4; c++) acc[a][b][c] = 0.0f;

    int wm = wid & 3, wn = wid >> 2;

    // kchunk stride in bytes along K: 64 halves = 128 bytes
#define LOAD_STAGE(SB, KC)                                                    \
    do {                                                                      \
        const char* a0 = gA + (size_t)(KC)*128;                               \
        const char* b0 = gB + (size_t)(KC)*128;                               \
        _Pragma("unroll") for (int j = 0; j < 2; j++)                         \
            cp16((SB) + soL + j * 8192, a0 + (size_t)j * 64 * (K * 2));       \
        _Pragma("unroll") for (int j = 0; j < 4; j++)                         \
            cp16((SB) + OFF_B + soL + j * 8192, b0 + (size_t)j * 64 * (K * 2));\
    } while (0)

    uint32_t sb[4] = {sbase, sbase + STAGE_BYTES, sbase + 2 * STAGE_BYTES,
                      sbase + 3 * STAGE_BYTES};
    constexpr int kiters = K >> 6;
    LOAD_STAGE(sb[0], 0);
    cp_commit();
    LOAD_STAGE(sb[1], 1);
    cp_commit();
    LOAD_STAGE(sb[2], 2);
    cp_commit();

    // ---- precomputed swizzled ldsm offsets (stage-local) ----
    // bases have bits 5-6 clear pre-swizzle, so for kd = k16*32 (bits 5-6):
    //   sw(base + kd) = sw(base) ^ kd          (XOR, NOT add — add can carry
    //                                           through swizzled bits 4-6)
    uint32_t aOff[2], bOff[4];
    {
        uint32_t aBase =
            (uint32_t)((wm * 32 + (lane & 15)) * 128 + ((lane >> 4) & 1) * 16);
        uint32_t bBase =
            (uint32_t)((wn * 64 + (lane & 7) + ((lane >> 4) & 1) * 8) * 128 +
                       ((lane >> 3) & 1) * 16);
#pragma unroll
        for (int mf = 0; mf < 2; mf++) {
            uint32_t o = aBase + mf * 2048;
            aOff[mf] = o ^ ((o >> 3) & 0x70);
        }
#pragma unroll
        for (int np = 0; np < 4; np++) {
            uint32_t o = bBase + np * 2048;
            bOff[np] = (o ^ ((o >> 3) & 0x70)) + OFF_B;  // OFF_B bit14: XOR-safe
        }
    }

#pragma unroll 1
    for (int kc = 0; kc < kiters; kc++) {
        uint32_t s = sb[kc & 3];
        cp_wait<2>();
        __syncthreads();  // ring: stage loaded next was consumed last iter

        uint32_t af[2][2][4], bf[2][4][4];
        // prologue: fragments for k16=0
#pragma unroll
        for (int mf = 0; mf < 2; mf++) ldsm4(af[0][mf], s + aOff[mf]);
#pragma unroll
        for (int np = 0; np < 4; np++) ldsm4(bf[0][np], s + bOff[np]);

#pragma unroll
        for (int k16 = 0; k16 < 4; k16++) {
            int cur = k16 & 1, nxt = cur ^ 1;
            if (k16 < 3) {
                uint32_t kd = (uint32_t)(k16 + 1) * 32;
#pragma unroll
                for (int mf = 0; mf < 2; mf++)
                    ldsm4(af[nxt][mf], s + (aOff[mf] ^ kd));
#pragma unroll
                for (int np = 0; np < 4; np++)
                    ldsm4(bf[nxt][np], s + (bOff[np] ^ kd));
            }
#pragma unroll
            for (int mf = 0; mf < 2; mf++)
#pragma unroll
                for (int np = 0; np < 4; np++) {
                    mma16816(acc[mf][2 * np], af[cur][mf], bf[cur][np][0],
                             bf[cur][np][1]);
                    mma16816(acc[mf][2 * np + 1], af[cur][mf], bf[cur][np][2],
                             bf[cur][np][3]);
                }
        }
        if (kc + 3 < kiters) LOAD_STAGE(sb[(kc + 3) & 3], kc + 3);
        cp_commit();
    }

    // ---- epilogue ----
    int row0 = wm * 32 + (lane >> 2);
    if (FUSE_SILU) {
        // interleaved cols: even = up, odd = gate. h = up * gate * sigmoid(gate)
        size_t grow0 = (size_t)e * 1024 + mt * 128 + row0;
        int hcol = nt * 128 + wn * 32 + (lane & 3);
#pragma unroll
        for (int mf = 0; mf < 2; mf++)
#pragma unroll
            for (int nf = 0; nf < 8; nf++) {
                size_t r = grow0 + mf * 16;
                int hc = hcol + nf * 4;
                float u0 = acc[mf][nf][0], g0 = acc[mf][nf][1];
                float u1 = acc[mf][nf][2], g1 = acc[mf][nf][3];
                float h0 = u0 * g0 * (1.0f / (1.0f + __expf(-g0)));
                float h1 = u1 * g1 * (1.0f / (1.0f + __expf(-g1)));
                H[r * H_DIM + hc] = __float2half(h0);
                H[(r + 8) * H_DIM + hc] = __float2half(h1);
            }
    } else {
        float* pC = C + ((size_t)e * 1024 + mt * 128) * 2048 + nt * 256;
        int col0 = wn * 64 + (lane & 3) * 2;
#pragma unroll
        for (int mf = 0; mf < 2; mf++)
#pragma unroll
            for (int nf = 0; nf < 8; nf++) {
                int r = row0 + mf * 16, c = col0 + nf * 8;
                float2 v0 = {acc[mf][nf][0], acc[mf][nf][1]};
                float2 v1 = {acc[mf][nf][2], acc[mf][nf][3]};
                *reinterpret_cast<float2*>(pC + (size_t)r * 2048 + c) = v0;
                *reinterpret_cast<float2*>(pC + (size_t)(r + 8) * 2048 + c) = v1;
            }
    }
#undef LOAD_STAGE
}

// ------------------------- launch ------------------------------------------
extern "C" void kernel_launch(void* const* d_in, const int* in_sizes, int n_in,
                              void* d_out, int out_size) {
    (void)in_sizes; (void)n_in; (void)out_size;
    const float* x = (const float*)d_in[0];
    const float* w1 = (const float*)d_in[1];
    const float* w2 = (const float*)d_in[2];
    float* out = (float*)d_out;

    cudaFuncSetAttribute(gemmf_kernel<D_DIM, true>,
                         cudaFuncAttributeMaxDynamicSharedMemorySize, GEMM_SMEM);
    cudaFuncSetAttribute(gemmf_kernel<H_DIM, false>,
                         cudaFuncAttributeMaxDynamicSharedMemorySize, GEMM_SMEM);

    __half *xh, *w1h, *w2th, *hh;
    cudaGetSymbolAddress((void**)&xh, g_xh);
    cudaGetSymbolAddress((void**)&w1h, g_w1h);
    cudaGetSymbolAddress((void**)&w2th, g_w2th);
    cudaGetSymbolAddress((void**)&hh, g_hh);

    // pre-pass: x -> fp16; w1 -> interleaved fp16; w2 -> transposed fp16
    cvt_kernel<<<32768, 256>>>(x, xh);
    interleave_cvt_kernel<<<65536, 256>>>(w1, w1h);
    transpose_cvt_kernel<<<dim3(64, 32, 16), dim3(32, 8)>>>(w2, w2th);

    // GEMM1: up/gate + fused silu -> h (fp16). grid: E * 8mt * 8nt
    gemmf_kernel<D_DIM, true><<<N_EXP * 64, 512, GEMM_SMEM>>>(
        xh, w1h, nullptr, hh);
    // GEMM2: out = h @ w2t^T. grid: E * 8mt * 8nt
    gemmf_kernel<H_DIM, false><<<N_EXP * 64, 512, GEMM_SMEM>>>(
        hh, w2th, out, nullptr);
}

// round 10
// speedup vs baseline: 2.5144x; 1.0716x over previous
#include <cuda_runtime.h>
#include <cuda_fp16.h>
#include <stdint.h>

#define N_TOK 16384
#define D_DIM 2048
#define H_DIM 1024
#define N_EXP 16

// ------------------------- scratch (device globals; no allocs) -------------
__device__ __half g_xh[(size_t)N_TOK * D_DIM];
__device__ __half g_w1h[(size_t)N_EXP * 2 * H_DIM * D_DIM];  // row-interleaved up/gate
__device__ __half g_w2th[(size_t)N_EXP * D_DIM * H_DIM];     // transposed w_down
__device__ __half g_hh[(size_t)N_TOK * H_DIM];

// ------------------------- PTX helpers (compute_103-legal only) ------------
__device__ __forceinline__ uint32_t smem_u32(const void* p) {
    uint32_t a;
    asm("{ .reg .u64 t; cvta.to.shared.u64 t, %1; cvt.u32.u64 %0, t; }"
        : "=r"(a) : "l"(p));
    return a;
}

__device__ __forceinline__ void cp16(uint32_t dst, const void* src) {
    asm volatile("cp.async.cg.shared.global [%0], [%1], 16;\n"
                 :: "r"(dst), "l"(src));
}
__device__ __forceinline__ void cp_commit() {
    asm volatile("cp.async.commit_group;\n" ::: "memory");
}
template <int NN>
__device__ __forceinline__ void cp_wait() {
    asm volatile("cp.async.wait_group %0;\n" :: "n"(NN) : "memory");
}

__device__ __forceinline__ void ldsm4(uint32_t* r, uint32_t addr) {
    asm volatile("ldmatrix.sync.aligned.m8n8.x4.shared.b16 {%0,%1,%2,%3}, [%4];"
                 : "=r"(r[0]), "=r"(r[1]), "=r"(r[2]), "=r"(r[3]) : "r"(addr));
}

__device__ __forceinline__ void mma16816(float* c, const uint32_t* a,
                                         uint32_t b0, uint32_t b1) {
    asm volatile(
        "mma.sync.aligned.m16n8k16.row.col.f32.f16.f16.f32 "
        "{%0,%1,%2,%3}, {%4,%5,%6,%7}, {%8,%9}, {%0,%1,%2,%3};"
        : "+f"(c[0]), "+f"(c[1]), "+f"(c[2]), "+f"(c[3])
        : "r"(a[0]), "r"(a[1]), "r"(a[2]), "r"(a[3]), "r"(b0), "r"(b1));
}

// ------------------------- pre-pass kernels --------------------------------
__global__ void __launch_bounds__(256) cvt_kernel(
    const float* __restrict__ src, __half* __restrict__ dst) {
    size_t i = (size_t)blockIdx.x * blockDim.x + threadIdx.x;
    float4 v = reinterpret_cast<const float4*>(src)[i];
    __half hv[4];
    float f[4] = {v.x, v.y, v.z, v.w};
#pragma unroll
    for (int k = 0; k < 4; k++) hv[k] = __float2half(f[k]);
    reinterpret_cast<uint2*>(dst)[i] = *reinterpret_cast<uint2*>(hv);
}

// w1 [E,2048,D] (up rows 0-1023, gate 1024-2047) -> row-interleaved fp16
__global__ void __launch_bounds__(256) interleave_cvt_kernel(
    const float* __restrict__ w, __half* __restrict__ dst) {
    size_t i = (size_t)blockIdx.x * blockDim.x + threadIdx.x;  // float4 idx
    size_t row = i >> 9;
    size_t c4 = (i & 511) << 2;
    int e = (int)(row >> 11);
    int r = (int)(row & 2047);
    int nr = (r < 1024) ? (2 * r) : (2 * (r - 1024) + 1);
    float4 v = *reinterpret_cast<const float4*>(w + row * D_DIM + c4);
    __half hv[4];
    float f[4] = {v.x, v.y, v.z, v.w};
#pragma unroll
    for (int k = 0; k < 4; k++) hv[k] = __float2half(f[k]);
    size_t o4 = (((size_t)e * 2048 + nr) * D_DIM + c4) >> 2;
    reinterpret_cast<uint2*>(dst)[o4] = *reinterpret_cast<uint2*>(hv);
}

// w_down [E,H,D] -> w2t [E,D,H] fp16
__global__ void __launch_bounds__(256) transpose_cvt_kernel(
    const float* __restrict__ w, __half* __restrict__ th) {
    __shared__ float tile[32][33];
    int e = blockIdx.z, hb = blockIdx.y, db = blockIdx.x;
    int tx = threadIdx.x, ty = threadIdx.y;  // 32 x 8
    const float* src = w + ((size_t)e * H_DIM + hb * 32) * D_DIM + db * 32;
#pragma unroll
    for (int j = 0; j < 32; j += 8)
        tile[ty + j][tx] = src[(size_t)(ty + j) * D_DIM + tx];
    __syncthreads();
    size_t ob = ((size_t)e * D_DIM + db * 32) * H_DIM + hb * 32;
#pragma unroll
    for (int j = 0; j < 32; j += 8)
        th[ob + (size_t)(ty + j) * H_DIM + tx] = __float2half(tile[tx][ty + j]);
}

// ------------------------- GEMM (fp16, mma.sync) ---------------------------
// C = A x B^T.  CTA tile 128(m) x 128(n), 256 threads (8 warps, 4m x 2n,
// warp tile 32x64). kchunk 64 (128B rows, SW128). 3-stage ring, 1
// barrier/chunk, 2 CTAs/SM (cross-CTA barrier hiding). K templated.
#define OFF_B  16384
#define STAGE_BYTES 32768            // A(16K) + B(16K)
#define GEMM_SMEM (3 * STAGE_BYTES)  // 96KB -> 2 CTAs/SM

template <int K, bool FUSE_SILU>
__global__ void __launch_bounds__(256, 2) gemmf_kernel(
    const __half* __restrict__ A, const __half* __restrict__ B,
    float* __restrict__ C, __half* __restrict__ H) {
    extern __shared__ char smem[];
    uint32_t sbase = smem_u32(smem);
    int tid = threadIdx.x, wid = tid >> 5, lane = tid & 31;
    int bx = blockIdx.x;
    int e = bx >> 7, rr = bx & 127, mt = rr >> 4, nt = rr & 15;

    // per-thread loader global pointers (bytes); constant strides thereafter
    int lrow = tid >> 3, lc16 = tid & 7;  // lrow 0..31, lc16 0..7
    const char* gA = (const char*)(A + ((size_t)e * 1024 + mt * 128 + lrow) * K +
                                   lc16 * 8);
    const char* gB = (const char*)(B + ((size_t)e * 2048 + nt * 128 + lrow) * K +
                                   lc16 * 8);
    // per-thread loader smem offset (swizzled once; +j*4096 carry-free since
    // soL < 4096)
    uint32_t soL = (uint32_t)(lrow * 128 + lc16 * 16);
    soL ^= (soL >> 3) & 0x70;

    float acc[2][8][4];
#pragma unroll
    for (int a = 0; a < 2; a++)
#pragma unroll
        for (int b = 0; b < 8; b++)
#pragma unroll
            for (int c = 0; c < 4; c++) acc[a][b][c] = 0.0f;

    int wm = wid & 3, wn = wid >> 2;  // 4m x 2n

    // kchunk stride in bytes along K: 64 halves = 128 bytes
#define LOAD_STAGE(SB, KC)                                                    \
    do {                                                                      \
        const char* a0 = gA + (size_t)(KC)*128;                               \
        const char* b0 = gB + (size_t)(KC)*128;                               \
        _Pragma("unroll") for (int j = 0; j < 4; j++)                         \
            cp16((SB) + soL + j * 4096, a0 + (size_t)j * 32 * (K * 2));       \
        _Pragma("unroll") for (int j = 0; j < 4; j++)                         \
            cp16((SB) + OFF_B + soL + j * 4096, b0 + (size_t)j * 32 * (K * 2));\
    } while (0)

    uint32_t sb[3] = {sbase, sbase + STAGE_BYTES, sbase + 2 * STAGE_BYTES};
    constexpr int kiters = K >> 6;
    LOAD_STAGE(sb[0], 0);
    cp_commit();
    LOAD_STAGE(sb[1], 1);
    cp_commit();

    // ---- precomputed swizzled ldsm offsets (stage-local) ----
    // bases have bits 5-6 clear pre-swizzle, so for kd = k16*32 (bits 5-6):
    //   sw(base + kd) = sw(base) ^ kd   (XOR; add could carry through
    //                                    swizzled bits 4-6)
    uint32_t aOff[2], bOff[4];
    {
        uint32_t aBase =
            (uint32_t)((wm * 32 + (lane & 15)) * 128 + ((lane >> 4) & 1) * 16);
        uint32_t bBase =
            (uint32_t)((wn * 64 + (lane & 7) + ((lane >> 4) & 1) * 8) * 128 +
                       ((lane >> 3) & 1) * 16);
#pragma unroll
        for (int mf = 0; mf < 2; mf++) {
            uint32_t o = aBase + mf * 2048;
            aOff[mf] = o ^ ((o >> 3) & 0x70);
        }
#pragma unroll
        for (int np = 0; np < 4; np++) {
            uint32_t o = bBase + np * 2048;
            bOff[np] = (o ^ ((o >> 3) & 0x70)) + OFF_B;  // OFF_B bit14: safe
        }
    }

#pragma unroll 1
    for (int kc = 0; kc < kiters; kc++) {
        uint32_t s = sb[kc % 3];
        cp_wait<1>();
        __syncthreads();  // ring: stage loaded below was consumed last iter

        uint32_t af[2][2][4], bf[2][4][4];
        // prologue: fragments for k16=0
#pragma unroll
        for (int mf = 0; mf < 2; mf++) ldsm4(af[0][mf], s + aOff[mf]);
#pragma unroll
        for (int np = 0; np < 4; np++) ldsm4(bf[0][np], s + bOff[np]);

#pragma unroll
        for (int k16 = 0; k16 < 4; k16++) {
            int cur = k16 & 1, nxt = cur ^ 1;
            if (k16 < 3) {
                uint32_t kd = (uint32_t)(k16 + 1) * 32;
#pragma unroll
                for (int mf = 0; mf < 2; mf++)
                    ldsm4(af[nxt][mf], s + (aOff[mf] ^ kd));
#pragma unroll
                for (int np = 0; np < 4; np++)
                    ldsm4(bf[nxt][np], s + (bOff[np] ^ kd));
            }
#pragma unroll
            for (int mf = 0; mf < 2; mf++)
#pragma unroll
                for (int np = 0; np < 4; np++) {
                    mma16816(acc[mf][2 * np], af[cur][mf], bf[cur][np][0],
                             bf[cur][np][1]);
                    mma16816(acc[mf][2 * np + 1], af[cur][mf], bf[cur][np][2],
                             bf[cur][np][3]);
                }
        }
        if (kc + 2 < kiters) LOAD_STAGE(sb[(kc + 2) % 3], kc + 2);
        cp_commit();
    }

    // ---- epilogue ----
    int row0 = wm * 32 + (lane >> 2);
    if (FUSE_SILU) {
        // interleaved cols: even = up, odd = gate. h = up * gate * sigmoid(gate)
        size_t grow0 = (size_t)e * 1024 + mt * 128 + row0;
        int hcol = nt * 64 + wn * 32 + (lane & 3);
#pragma unroll
        for (int mf = 0; mf < 2; mf++)
#pragma unroll
            for (int nf = 0; nf < 8; nf++) {
                size_t r = grow0 + mf * 16;
                int hc = hcol + nf * 4;
                float u0 = acc[mf][nf][0], g0 = acc[mf][nf][1];
                float u1 = acc[mf][nf][2], g1 = acc[mf][nf][3];
                float h0 = u0 * g0 * (1.0f / (1.0f + __expf(-g0)));
                float h1 = u1 * g1 * (1.0f / (1.0f + __expf(-g1)));
                H[r * H_DIM + hc] = __float2half(h0);
                H[(r + 8) * H_DIM + hc] = __float2half(h1);
            }
    } else {
        float* pC = C + ((size_t)e * 1024 + mt * 128) * 2048 + nt * 128;
        int col0 = wn * 64 + (lane & 3) * 2;
#pragma unroll
        for (int mf = 0; mf < 2; mf++)
#pragma unroll
            for (int nf = 0; nf < 8; nf++) {
                int r = row0 + mf * 16, c = col0 + nf * 8;
                float2 v0 = {acc[mf][nf][0], acc[mf][nf][1]};
                float2 v1 = {acc[mf][nf][2], acc[mf][nf][3]};
                *reinterpret_cast<float2*>(pC + (size_t)r * 2048 + c) = v0;
                *reinterpret_cast<float2*>(pC + (size_t)(r + 8) * 2048 + c) = v1;
            }
    }
#undef LOAD_STAGE
}

// ------------------------- launch ------------------------------------------
extern "C" void kernel_launch(void* const* d_in, const int* in_sizes, int n_in,
                              void* d_out, int out_size) {
    (void)in_sizes; (void)n_in; (void)out_size;
    const float* x = (const float*)d_in[0];
    const float* w1 = (const float*)d_in[1];
    const float* w2 = (const float*)d_in[2];
    float* out = (float*)d_out;

    cudaFuncSetAttribute(gemmf_kernel<D_DIM, true>,
                         cudaFuncAttributeMaxDynamicSharedMemorySize, GEMM_SMEM);
    cudaFuncSetAttribute(gemmf_kernel<H_DIM, false>,
                         cudaFuncAttributeMaxDynamicSharedMemorySize, GEMM_SMEM);

    __half *xh, *w1h, *w2th, *hh;
    cudaGetSymbolAddress((void**)&xh, g_xh);
    cudaGetSymbolAddress((void**)&w1h, g_w1h);
    cudaGetSymbolAddress((void**)&w2th, g_w2th);
    cudaGetSymbolAddress((void**)&hh, g_hh);

    // pre-pass: x -> fp16; w1 -> interleaved fp16; w2 -> transposed fp16
    cvt_kernel<<<32768, 256>>>(x, xh);
    interleave_cvt_kernel<<<65536, 256>>>(w1, w1h);
    transpose_cvt_kernel<<<dim3(64, 32, 16), dim3(32, 8)>>>(w2, w2th);

    // GEMM1: up/gate + fused silu -> h (fp16). grid: E * 8mt * 16nt
    gemmf_kernel<D_DIM, true><<<N_EXP * 128, 256, GEMM_SMEM>>>(
        xh, w1h, nullptr, hh);
    // GEMM2: out = h @ w2t^T. grid: E * 8mt * 16nt
    gemmf_kernel<H_DIM, false><<<N_EXP * 128, 256, GEMM_SMEM>>>(
        hh, w2th, out, nullptr);
}